// round 15
// baseline (speedup 1.0000x reference)
#include <cuda_runtime.h>
#include <stdint.h>

#define NUM_BUCKETS 4000000u
#define NUM_FIELDS  63
#define NUM_SEG     64
#define SEQ         500
#define BATCH       16384
#define GROUPS      (BATCH * SEQ / 4)   // 2,048,000 vec4 groups
#define GPR         (SEQ / 4)           // 125 groups per row
#define THREADS     256
#define TILE_GROUPS 512                 // groups per CTA (2 per thread)
#define TILE_ELEMS  2048                // elements per CTA
#define NBLOCKS     (GROUPS / TILE_GROUPS)   // 4000
#define OUT_ELEMS   (BATCH * NUM_FIELDS)

// Zero the (poisoned) output: 258,048 float4, one per thread.
__global__ __launch_bounds__(256) void zero_out_kernel(float4* __restrict__ o4) {
    const int i = blockIdx.x * blockDim.x + threadIdx.x;
    if (i < OUT_ELEMS / 4)
        o4[i] = make_float4(0.f, 0.f, 0.f, 0.f);
}

// Strategy: the random 4B table gathers are an irreducible ~256 L1tex
// wavefronts per warp. R14 showed the contiguous stream loads (idx/fld/val,
// LDG.128) add another ~160 wavefronts/warp on the SAME pipe. So move the
// streams onto the TMA bulk-copy path (cp.async.bulk -> UBLKCP, no per-lane
// L1tex wavefronts) into smem, and read them back over the separate shared
// crossbar. Scatter remains no-return global atomics (REDG) to the 4MB
// L2-resident output; field==0 (padding) skips both gather and scatter.
__global__ __launch_bounds__(THREADS) void wide_scatter_kernel(
    const void* __restrict__ idx_raw,
    const void* __restrict__ fld_raw,
    const float* __restrict__ values,
    const float* __restrict__ table,
    float* __restrict__ out)
{
    __shared__ alignas(16) unsigned char s_idx[TILE_ELEMS * 8];  // 16 KB
    __shared__ alignas(16) unsigned char s_fld[TILE_ELEMS * 8];  // 16 KB
    __shared__ alignas(16) float         s_val[TILE_ELEMS];      //  8 KB
    __shared__ uint64_t s_mbar;
    __shared__ int s_is64;

    const int t = threadIdx.x;
    const uint32_t mbar = (uint32_t)__cvta_generic_to_shared(&s_mbar);

    // dtype probe (warp 0): lane L reads odd word 2L+1 of indexes (first
    // 256B, broadcast hit). int64 data (ids < 2^32): all odd words zero.
    // int32 data uniform < 1e8: P(all 32 zero) ~ 1e-256.
    if (t < 32) {
        const unsigned probe = __ldg((const unsigned int*)idx_raw + 2 * t + 1);
        const bool is64 = (__ballot_sync(0xffffffffu, probe != 0u) == 0u);
        if (t == 0) {
            s_is64 = is64 ? 1 : 0;
            asm volatile("mbarrier.init.shared.b64 [%0], 1;"
                         :: "r"(mbar) : "memory");
        }
    }
    __syncthreads();   // mbarrier + s_is64 visible to all

    if (t == 0) {
        const int is64 = s_is64;
        const unsigned esz    = is64 ? 8u : 4u;
        const unsigned ibytes = TILE_ELEMS * esz;
        const unsigned vbytes = TILE_ELEMS * 4u;
        const long ebase = (long)blockIdx.x * TILE_ELEMS;

        asm volatile("mbarrier.arrive.expect_tx.shared.b64 _, [%0], %1;"
                     :: "r"(mbar), "r"(2u * ibytes + vbytes) : "memory");

        const uint32_t d_i = (uint32_t)__cvta_generic_to_shared(s_idx);
        const uint32_t d_f = (uint32_t)__cvta_generic_to_shared(s_fld);
        const uint32_t d_v = (uint32_t)__cvta_generic_to_shared(s_val);
        const char* src_i = (const char*)idx_raw + ebase * esz;
        const char* src_f = (const char*)fld_raw + ebase * esz;
        const char* src_v = (const char*)values  + ebase * 4;

        asm volatile("cp.async.bulk.shared::cluster.global.mbarrier::complete_tx::bytes [%0], [%1], %2, [%3];"
                     :: "r"(d_i), "l"(src_i), "r"(ibytes), "r"(mbar) : "memory");
        asm volatile("cp.async.bulk.shared::cluster.global.mbarrier::complete_tx::bytes [%0], [%1], %2, [%3];"
                     :: "r"(d_f), "l"(src_f), "r"(ibytes), "r"(mbar) : "memory");
        asm volatile("cp.async.bulk.shared::cluster.global.mbarrier::complete_tx::bytes [%0], [%1], %2, [%3];"
                     :: "r"(d_v), "l"(src_v), "r"(vbytes), "r"(mbar) : "memory");
    }

    // All threads wait for the tile (phase parity 0; one phase per launch).
    {
        uint32_t done;
        do {
            asm volatile(
                "{\n\t.reg .pred p;\n\t"
                "mbarrier.try_wait.parity.acquire.cta.shared::cta.b64 p, [%1], %2, 0x989680;\n\t"
                "selp.b32 %0, 1, 0, p;\n\t}"
                : "=r"(done) : "r"(mbar), "r"(0u) : "memory");
        } while (!done);
    }

    const int is64 = s_is64;
    const unsigned g0 = (unsigned)blockIdx.x * TILE_GROUPS + t;   // global group ids
    const unsigned g1 = g0 + THREADS;
    const unsigned row0 = g0 / GPR;        // groups never straddle rows
    const unsigned row1 = g1 / GPR;

    unsigned ia[8], fa[8];
    if (is64) {
        const ulonglong2* __restrict__ ip = (const ulonglong2*)s_idx;
        const ulonglong2* __restrict__ fp = (const ulonglong2*)s_fld;
        const int h0 = t * 2, h1 = (t + THREADS) * 2;
        ulonglong2 a0 = ip[h0], a1 = ip[h0 + 1], a2 = ip[h1], a3 = ip[h1 + 1];
        ulonglong2 b0 = fp[h0], b1 = fp[h0 + 1], b2 = fp[h1], b3 = fp[h1 + 1];
        ia[0] = (unsigned)a0.x; ia[1] = (unsigned)a0.y;
        ia[2] = (unsigned)a1.x; ia[3] = (unsigned)a1.y;
        ia[4] = (unsigned)a2.x; ia[5] = (unsigned)a2.y;
        ia[6] = (unsigned)a3.x; ia[7] = (unsigned)a3.y;
        fa[0] = (unsigned)b0.x; fa[1] = (unsigned)b0.y;
        fa[2] = (unsigned)b1.x; fa[3] = (unsigned)b1.y;
        fa[4] = (unsigned)b2.x; fa[5] = (unsigned)b2.y;
        fa[6] = (unsigned)b3.x; fa[7] = (unsigned)b3.y;
    } else {
        const uint4* __restrict__ ip = (const uint4*)s_idx;
        const uint4* __restrict__ fp = (const uint4*)s_fld;
        uint4 a0 = ip[t], a1 = ip[t + THREADS];
        uint4 b0 = fp[t], b1 = fp[t + THREADS];
        ia[0] = a0.x; ia[1] = a0.y; ia[2] = a0.z; ia[3] = a0.w;
        ia[4] = a1.x; ia[5] = a1.y; ia[6] = a1.z; ia[7] = a1.w;
        fa[0] = b0.x; fa[1] = b0.y; fa[2] = b0.z; fa[3] = b0.w;
        fa[4] = b1.x; fa[5] = b1.y; fa[6] = b1.z; fa[7] = b1.w;
    }

    const float4* __restrict__ vp = (const float4*)s_val;
    const float4 v0 = vp[t];
    const float4 v1 = vp[t + THREADS];
    const float vv[8] = { v0.x, v0.y, v0.z, v0.w, v1.x, v1.y, v1.z, v1.w };

    // Random gathers (L2-only; skip padding field 0 -> fewer sectors).
    float e[8];
    #pragma unroll
    for (int k = 0; k < 8; k++) {
        const unsigned f = fa[k] & (NUM_SEG - 1);
        e[k] = f ? __ldcg(table + (ia[k] % NUM_BUCKETS)) : 0.f;
    }

    // Scatter: field f -> out[row, f-1] via no-return atomics (REDG in LTS).
    float* __restrict__ o0 = out + (long)row0 * NUM_FIELDS - 1;
    float* __restrict__ o1 = out + (long)row1 * NUM_FIELDS - 1;
    #pragma unroll
    for (int k = 0; k < 4; k++) {
        const unsigned f = fa[k] & (NUM_SEG - 1);
        if (f) atomicAdd(o0 + f, e[k] * vv[k]);
    }
    #pragma unroll
    for (int k = 4; k < 8; k++) {
        const unsigned f = fa[k] & (NUM_SEG - 1);
        if (f) atomicAdd(o1 + f, e[k] * vv[k]);
    }
}

extern "C" void kernel_launch(void* const* d_in, const int* in_sizes, int n_in,
                              void* d_out, int out_size) {
    // metadata order: indexes, fields, values, emb_table
    const void*  d_idx   = d_in[0];
    const void*  d_fld   = d_in[1];
    const float* d_val   = (const float*)d_in[2];
    const float* d_table = (const float*)d_in[3];
    float*       out     = (float*)d_out;

    zero_out_kernel<<<(OUT_ELEMS / 4 + 255) / 256, 256>>>((float4*)out);
    wide_scatter_kernel<<<NBLOCKS, THREADS>>>(d_idx, d_fld, d_val, d_table, out);
}

// round 16
// speedup vs baseline: 1.4796x; 1.4796x over previous
#include <cuda_runtime.h>
#include <stdint.h>

#define NUM_BUCKETS 4000000u
#define NUM_FIELDS  63
#define NUM_SEG     64
#define SEQ         500
#define BATCH       16384
#define GROUPS      (BATCH * SEQ / 4)   // 2,048,000 vec4 groups
#define GPR         (SEQ / 4)           // 125 groups per row
#define HALF        (GROUPS / 2)        // 1,024,000 = 4000 CTAs x 256
#define OUT_ELEMS   (BATCH * NUM_FIELDS)

// Zero the (poisoned) output: 258,048 float4, one per thread.
__global__ __launch_bounds__(256) void zero_out_kernel(float4* __restrict__ o4) {
    const int i = blockIdx.x * blockDim.x + threadIdx.x;
    if (i < OUT_ELEMS / 4)
        o4[i] = make_float4(0.f, 0.f, 0.f, 0.f);
}

// Two vec4 groups (8 elements) per thread: g and g+HALF. All 8 random table
// gathers batched back-to-back (MLP=8) before consumption. Scatter goes
// straight to the 4MB L2-resident output via no-return global atomics (REDG,
// executed in the LTS atomic ALUs). Within each 4-element half (same row),
// duplicate fields are merged on the (idle) ALU/FMA pipes before scattering:
// fewer REDG lanes on the saturated LSU port and fewer same-address
// serializations at the L2 slice.
// dtype (int32 vs int64) detected inline per warp: lane L reads odd word 2L+1
// of indexes (first 256B, broadcast hit); int64 data (ids < 2^32) has all odd
// words zero; for int32 uniform < 1e8, P(all 32 zero) ~ 1e-256.
__global__ __launch_bounds__(256, 6) void wide_scatter_kernel(
    const void* __restrict__ idx_raw,
    const void* __restrict__ fld_raw,
    const float* __restrict__ values,
    const float* __restrict__ table,
    float* __restrict__ out)
{
    const int lane = threadIdx.x & 31;
    const unsigned probe = __ldg((const unsigned int*)idx_raw + 2 * lane + 1);
    const bool is64 = (__ballot_sync(0xffffffffu, probe != 0u) == 0u);

    const int g0 = blockIdx.x * blockDim.x + threadIdx.x;  // < HALF
    const int g1 = g0 + HALF;
    const unsigned row0 = (unsigned)g0 / GPR;              // groups never straddle rows
    const unsigned row1 = (unsigned)g1 / GPR;
    const long base0 = (long)g0 * 4;                       // 16B-aligned
    const long base1 = (long)g1 * 4;

    unsigned ia[8], fa[8];
    if (is64) {
        const ulonglong2* __restrict__ ip = (const ulonglong2*)idx_raw;
        const ulonglong2* __restrict__ fp = (const ulonglong2*)fld_raw;
        const long h0 = base0 >> 1, h1 = base1 >> 1;
        ulonglong2 a0 = __ldcs(&ip[h0]), a1 = __ldcs(&ip[h0 + 1]);
        ulonglong2 a2 = __ldcs(&ip[h1]), a3 = __ldcs(&ip[h1 + 1]);
        ulonglong2 b0 = __ldcs(&fp[h0]), b1 = __ldcs(&fp[h0 + 1]);
        ulonglong2 b2 = __ldcs(&fp[h1]), b3 = __ldcs(&fp[h1 + 1]);
        ia[0] = (unsigned)a0.x; ia[1] = (unsigned)a0.y;
        ia[2] = (unsigned)a1.x; ia[3] = (unsigned)a1.y;
        ia[4] = (unsigned)a2.x; ia[5] = (unsigned)a2.y;
        ia[6] = (unsigned)a3.x; ia[7] = (unsigned)a3.y;
        fa[0] = (unsigned)b0.x; fa[1] = (unsigned)b0.y;
        fa[2] = (unsigned)b1.x; fa[3] = (unsigned)b1.y;
        fa[4] = (unsigned)b2.x; fa[5] = (unsigned)b2.y;
        fa[6] = (unsigned)b3.x; fa[7] = (unsigned)b3.y;
    } else {
        const uint4* __restrict__ ip = (const uint4*)idx_raw;
        const uint4* __restrict__ fp = (const uint4*)fld_raw;
        const long q0 = base0 >> 2, q1 = base1 >> 2;
        uint4 a0 = __ldcs(&ip[q0]), a1 = __ldcs(&ip[q1]);
        uint4 b0 = __ldcs(&fp[q0]), b1 = __ldcs(&fp[q1]);
        ia[0] = a0.x; ia[1] = a0.y; ia[2] = a0.z; ia[3] = a0.w;
        ia[4] = a1.x; ia[5] = a1.y; ia[6] = a1.z; ia[7] = a1.w;
        fa[0] = b0.x; fa[1] = b0.y; fa[2] = b0.z; fa[3] = b0.w;
        fa[4] = b1.x; fa[5] = b1.y; fa[6] = b1.z; fa[7] = b1.w;
    }

    const float4 v0 = __ldcs((const float4*)(values + base0));
    const float4 v1 = __ldcs((const float4*)(values + base1));

    // 8 random gathers batched (L2-only: table has ~1% L1 residency).
    float e[8];
    #pragma unroll
    for (int k = 0; k < 8; k++)
        e[k] = __ldcg(table + (ia[k] % NUM_BUCKETS));

    // Products + field ids (0 = padding -> dropped).
    float p[8] = { e[0] * v0.x, e[1] * v0.y, e[2] * v0.z, e[3] * v0.w,
                   e[4] * v1.x, e[5] * v1.y, e[6] * v1.z, e[7] * v1.w };
    unsigned f[8];
    #pragma unroll
    for (int k = 0; k < 8; k++) f[k] = fa[k] & (NUM_SEG - 1);

    // Merge duplicate fields within each half (same output row) — pure
    // ALU/FMA work on otherwise-idle pipes; each merge removes one REDG.
    #pragma unroll
    for (int i = 0; i < 3; i++)
        #pragma unroll
        for (int j = i + 1; j < 4; j++)
            if (f[i] && f[j] == f[i]) { p[i] += p[j]; f[j] = 0; }
    #pragma unroll
    for (int i = 4; i < 7; i++)
        #pragma unroll
        for (int j = i + 1; j < 8; j++)
            if (f[i] && f[j] == f[i]) { p[i] += p[j]; f[j] = 0; }

    // Scatter: field f -> out[row, f-1] via no-return atomics (REDG in LTS).
    float* __restrict__ o0 = out + (long)row0 * NUM_FIELDS - 1;
    float* __restrict__ o1 = out + (long)row1 * NUM_FIELDS - 1;
    #pragma unroll
    for (int k = 0; k < 4; k++)
        if (f[k]) atomicAdd(o0 + f[k], p[k]);
    #pragma unroll
    for (int k = 4; k < 8; k++)
        if (f[k]) atomicAdd(o1 + f[k], p[k]);
}

extern "C" void kernel_launch(void* const* d_in, const int* in_sizes, int n_in,
                              void* d_out, int out_size) {
    // metadata order: indexes, fields, values, emb_table
    const void*  d_idx   = d_in[0];
    const void*  d_fld   = d_in[1];
    const float* d_val   = (const float*)d_in[2];
    const float* d_table = (const float*)d_in[3];
    float*       out     = (float*)d_out;

    zero_out_kernel<<<(OUT_ELEMS / 4 + 255) / 256, 256>>>((float4*)out);
    wide_scatter_kernel<<<HALF / 256, 256>>>(d_idx, d_fld, d_val, d_table, out);
}